// round 6
// baseline (speedup 1.0000x reference)
#include <cuda_runtime.h>
#include <math.h>
#include <stdint.h>

#define BN   4
#define VN   256
#define C1N  64
#define C2N  32
#define H0N  128
#define H2N  256

// ---------------- scratch ----------------
__device__ float g_A [BN*VN*H0N];
__device__ float g_Bv[BN*VN*H0N];
__device__ float g_x1[BN*VN*H0N];
__device__ float g_x2[BN*VN*H0N];
__device__ float g_P [BN*VN*H2N];
__device__ float g_Q [BN*VN*H2N];

__device__ __forceinline__ uint32_t f32_to_tf32(float x) {
    uint32_t r;
    asm("cvt.rna.tf32.f32 %0, %1;" : "=r"(r) : "f"(x));
    return r;
}
__device__ __forceinline__ void mma_16x8x8(float* c, const uint32_t* a, const uint32_t* b) {
    asm volatile("mma.sync.aligned.m16n8k8.row.col.f32.tf32.tf32.f32 "
        "{%0,%1,%2,%3}, {%4,%5,%6,%7}, {%8,%9}, {%0,%1,%2,%3};"
        : "+f"(c[0]), "+f"(c[1]), "+f"(c[2]), "+f"(c[3])
        : "r"(a[0]), "r"(a[1]), "r"(a[2]), "r"(a[3]), "r"(b[0]), "r"(b[1]));
}
__device__ __forceinline__ void ldsm_x4(uint32_t* r, uint32_t addr) {
    asm volatile("ldmatrix.sync.aligned.m8n8.x4.shared.b16 {%0,%1,%2,%3}, [%4];"
        : "=r"(r[0]), "=r"(r[1]), "=r"(r[2]), "=r"(r[3]) : "r"(addr));
}
__device__ __forceinline__ uint32_t smem_u32(const void* p) {
    return (uint32_t)__cvta_generic_to_shared(p);
}

// SMEM layout in 4-byte words.
// W1eT: [128 n][k] stride 36 ; W2T: [128 n][k] stride 132 (both n-major)
// E:    [128 j][k] stride 36 ; H1:  [128 j][k] stride 132 (row/j-major)
#define OFF_W1E 0
#define OFF_W2  (OFF_W1E + 128*36)     //  4608
#define OFF_E   (OFF_W2  + 128*132)    // 21504
#define OFF_H1  (OFF_E   + 128*36)     // 26112
#define OFF_A   (OFF_H1  + 128*132)    // 43008
#define OFF_B2  (OFF_A + 128)
#define OFF_ADJ (OFF_B2 + 128)
#define OFF_RED (OFF_ADJ + 256)
#define SMEM_WORDS (OFF_RED + 8*132)
#define SMEM_BYTES (SMEM_WORDS * 4)

// ---------------------------------------------------------------------------
// prep_node tiled: 64 CTAs x 16 nodes, 128 threads. W1 read once per CTA.
template<int C>
__global__ void prep_node2(const float* __restrict__ x,
                           const float* __restrict__ W1,
                           const float* __restrict__ b1,
                           float* __restrict__ A,
                           float* __restrict__ Bout)
{
    __shared__ float sx[16 * C];
    const int ni0 = blockIdx.x * 16;
    const int h   = threadIdx.x;     // 128
    for (int idx = h; idx < 16 * C; idx += 128)
        sx[idx] = x[(size_t)ni0 * C + idx];
    __syncthreads();
    float accA[16], accB[16];
#pragma unroll
    for (int r = 0; r < 16; r++) { accA[r] = 0.f; accB[r] = 0.f; }
#pragma unroll 2
    for (int c = 0; c < C; c++) {
        float wa = W1[c * 128 + h];
        float wb = W1[(C + c) * 128 + h];
        float d  = wa - wb;
#pragma unroll
        for (int r = 0; r < 16; r++) {
            float xa = sx[r * C + c];
            accA[r] += xa * d;
            accB[r] += xa * wb;
        }
    }
    const float bb = b1[h];
#pragma unroll
    for (int r = 0; r < 16; r++) {
        A   [(size_t)(ni0 + r) * 128 + h] = accA[r] + bb;
        Bout[(size_t)(ni0 + r) * 128 + h] = accB[r];
    }
}

// ---------------------------------------------------------------------------
// Fused edgeconv: mma.sync tf32 + ldmatrix. One CTA per (b,i), 512 threads.
// 16 warps = 8 M-groups (16 rows each) x 2 N-groups (64 cols each).
__global__ __launch_bounds__(512, 1)
void fused_ec_mma(const int*   __restrict__ adj,
                  const float* __restrict__ e,       // (B,V,V,32)
                  const float* __restrict__ A,
                  const float* __restrict__ Bnode,
                  const float* __restrict__ W1e,     // (32,128)
                  const float* __restrict__ W2,      // (128,128)
                  const float* __restrict__ b2,
                  float* __restrict__ xout)
{
    extern __shared__ float smem[];
    uint32_t* s32 = (uint32_t*)smem;
    const uint32_t sbase = smem_u32(smem);
    const int tid  = threadIdx.x;
    const int lane = tid & 31;
    const int wid  = tid >> 5;
    const int gid  = lane >> 2;
    const int tig  = lane & 3;
    const int WM   = wid & 7;        // rows WM*16 .. +15
    const int WN   = wid >> 3;       // cols WN*64 .. +63
    const int m0   = WM * 16;
    const int n0   = WN * 64;
    const int bi   = blockIdx.x;     // b*256 + i
    const int b    = bi >> 8;

    // per-lane ldmatrix base addresses (byte)
    const int lt = lane >> 3, lr = lane & 7;
    // A tiles: t0={r0-7,k0-3} t1={r8-15,k0-3} t2={r0-7,k4-7} t3={r8-15,k4-7}
    const int arow  = m0 + ((lt & 1) << 3) + lr;
    const int aword = (lt >> 1) << 2;
    const uint32_t aE = sbase + (uint32_t)(OFF_E  + arow * 36  + aword) * 4;
    const uint32_t aH = sbase + (uint32_t)(OFF_H1 + arow * 132 + aword) * 4;
    // B tiles: t0={nt0,k0-3} t1={nt0,k4-7} t2={nt1,k0-3} t3={nt1,k4-7}
    const int brow  = n0 + ((lt >> 1) << 3) + lr;
    const int bword = (lt & 1) << 2;
    const uint32_t bW1 = sbase + (uint32_t)(OFF_W1E + brow * 36  + bword) * 4;
    const uint32_t bW2 = sbase + (uint32_t)(OFF_W2  + brow * 132 + bword) * 4;

    // ---- stage W1e^T (n-major, stride 36) ----
    {
        int k  = tid >> 4;               // 0..31
        int ng = (tid & 15) * 8;
        const float4* src = (const float4*)(W1e + k * 128 + ng);
        float4 v0 = src[0], v1 = src[1];
        uint32_t vv[8] = { f32_to_tf32(v0.x), f32_to_tf32(v0.y), f32_to_tf32(v0.z), f32_to_tf32(v0.w),
                           f32_to_tf32(v1.x), f32_to_tf32(v1.y), f32_to_tf32(v1.z), f32_to_tf32(v1.w) };
#pragma unroll
        for (int i = 0; i < 8; i++)
            s32[OFF_W1E + (ng + i) * 36 + k] = vv[i];
    }
    // ---- stage W2^T (n-major, stride 132) ----
    {
        int k  = tid >> 2;               // 0..127
        int nq = (tid & 3) * 32;
        const float4* src = (const float4*)(W2 + k * 128 + nq);
#pragma unroll
        for (int c4 = 0; c4 < 8; c4++) {
            float4 v = src[c4];
            int n = nq + c4 * 4;
            s32[OFF_W2 + (n+0) * 132 + k] = f32_to_tf32(v.x);
            s32[OFF_W2 + (n+1) * 132 + k] = f32_to_tf32(v.y);
            s32[OFF_W2 + (n+2) * 132 + k] = f32_to_tf32(v.z);
            s32[OFF_W2 + (n+3) * 132 + k] = f32_to_tf32(v.w);
        }
    }
    if (tid < 128) {
        smem[OFF_A  + tid] = A[(size_t)bi * 128 + tid];
        smem[OFF_B2 + tid] = b2[tid];
    } else if (tid < 384) {
        ((int*)(smem + OFF_ADJ))[tid - 128] = adj[(size_t)bi * 256 + tid - 128];
    }

    float pmax = 0.0f;

    for (int chunk = 0; chunk < 2; chunk++) {
        const int j0 = chunk << 7;
        __syncthreads();

        // ---- stage E chunk (128 x 32, stride 36) ----
        {
            int row = tid >> 2;
            int cb  = (tid & 3) * 8;
            const float4* src = (const float4*)(e + ((size_t)bi * 256 + j0 + row) * 32 + cb);
            float4 v0 = src[0], v1 = src[1];
            uint32_t* d = s32 + OFF_E + row * 36 + cb;
            d[0] = f32_to_tf32(v0.x); d[1] = f32_to_tf32(v0.y);
            d[2] = f32_to_tf32(v0.z); d[3] = f32_to_tf32(v0.w);
            d[4] = f32_to_tf32(v1.x); d[5] = f32_to_tf32(v1.y);
            d[6] = f32_to_tf32(v1.z); d[7] = f32_to_tf32(v1.w);
        }
        __syncthreads();

        float acc[8][4];
#pragma unroll
        for (int nt = 0; nt < 8; nt++)
#pragma unroll
            for (int q = 0; q < 4; q++) acc[nt][q] = 0.f;

        // ---- GEMM1: D1 = E @ W1e  (K=32, 4 k-steps) ----
#pragma unroll
        for (int ks = 0; ks < 4; ks++) {
            uint32_t af[4];
            ldsm_x4(af, aE + ks * 32);
#pragma unroll
            for (int np = 0; np < 4; np++) {
                uint32_t bf[4];
                ldsm_x4(bf, bW1 + (uint32_t)np * (16 * 36 * 4) + ks * 32);
                mma_16x8x8(acc[np*2],     af, bf);
                mma_16x8x8(acc[np*2 + 1], af, bf + 2);
            }
        }

        // ---- epilogue 1: H1 = relu(D1 + A_i[n] + Bnode[j,n]) -> tf32 ----
        {
            const float* sA_ = smem + OFF_A;
            const int r_lo = m0 + gid;
            const int r_hi = r_lo + 8;
            const float2* blo = (const float2*)(Bnode + ((size_t)(b*256 + j0 + r_lo)) * 128);
            const float2* bhi = (const float2*)(Bnode + ((size_t)(b*256 + j0 + r_hi)) * 128);
#pragma unroll
            for (int nt = 0; nt < 8; nt++) {
                const int ncol = n0 + nt*8 + 2*tig;
                float2 bl = blo[ncol >> 1];
                float2 bh = bhi[ncol >> 1];
                float a0v = sA_[ncol], a1v = sA_[ncol + 1];
                float h00 = fmaxf(acc[nt][0] + a0v + bl.x, 0.f);
                float h01 = fmaxf(acc[nt][1] + a1v + bl.y, 0.f);
                float h10 = fmaxf(acc[nt][2] + a0v + bh.x, 0.f);
                float h11 = fmaxf(acc[nt][3] + a1v + bh.y, 0.f);
                uint32_t* d0 = s32 + OFF_H1 + r_lo * 132 + ncol;
                uint32_t* d1 = s32 + OFF_H1 + r_hi * 132 + ncol;
                d0[0] = f32_to_tf32(h00); d0[1] = f32_to_tf32(h01);
                d1[0] = f32_to_tf32(h10); d1[1] = f32_to_tf32(h11);
            }
        }
        __syncthreads();

#pragma unroll
        for (int nt = 0; nt < 8; nt++)
#pragma unroll
            for (int q = 0; q < 4; q++) acc[nt][q] = 0.f;

        // ---- GEMM2: D2 = H1 @ W2  (K=128, 16 k-steps) ----
#pragma unroll 4
        for (int ks = 0; ks < 16; ks++) {
            uint32_t af[4];
            ldsm_x4(af, aH + ks * 32);
#pragma unroll
            for (int np = 0; np < 4; np++) {
                uint32_t bf[4];
                ldsm_x4(bf, bW2 + (uint32_t)np * (16 * 132 * 4) + ks * 32);
                mma_16x8x8(acc[np*2],     af, bf);
                mma_16x8x8(acc[np*2 + 1], af, bf + 2);
            }
        }

        // ---- epilogue 2: bias+relu+mask, warp row-max -> red[WM][col] ----
        {
            const int* sAdj = (const int*)(smem + OFF_ADJ);
            const float* sb2_ = smem + OFF_B2;
            float* red = smem + OFF_RED;
            const bool kLo = sAdj[j0 + m0 + gid]     > 0;
            const bool kHi = sAdj[j0 + m0 + 8 + gid] > 0;
#pragma unroll
            for (int nt = 0; nt < 8; nt++) {
                const int ncol = n0 + nt*8 + 2*tig;
                const float bb0 = sb2_[ncol], bb1 = sb2_[ncol + 1];
                float vA = 0.f, vB = 0.f;
                if (kLo) { vA = fmaxf(vA, fmaxf(acc[nt][0] + bb0, 0.f));
                           vB = fmaxf(vB, fmaxf(acc[nt][1] + bb1, 0.f)); }
                if (kHi) { vA = fmaxf(vA, fmaxf(acc[nt][2] + bb0, 0.f));
                           vB = fmaxf(vB, fmaxf(acc[nt][3] + bb1, 0.f)); }
#pragma unroll
                for (int msk = 4; msk <= 16; msk <<= 1) {
                    vA = fmaxf(vA, __shfl_xor_sync(0xffffffffu, vA, msk));
                    vB = fmaxf(vB, __shfl_xor_sync(0xffffffffu, vB, msk));
                }
                if (gid == 0) {
                    red[WM * 132 + ncol]     = vA;
                    red[WM * 132 + ncol + 1] = vB;
                }
            }
        }
        __syncthreads();
        if (tid < 128) {
            float v = smem[OFF_RED + tid];
#pragma unroll
            for (int w = 1; w < 8; w++)
                v = fmaxf(v, smem[OFF_RED + w * 132 + tid]);
            pmax = fmaxf(pmax, v);
        }
    }

    if (tid < 128) xout[(size_t)bi * 128 + tid] = pmax;
}

// ---------------------------------------------------------------------------
// pair prep tiled: 64 CTAs x 16 rows, 256 threads. W3 read once per CTA.
__global__ void pair_prep2(const float* __restrict__ x,     // (B*V,128)
                           const float* __restrict__ W3,    // (256,256)
                           float* __restrict__ P,
                           float* __restrict__ Q)
{
    __shared__ float sx[16 * 128];
    const int ni0 = blockIdx.x * 16;
    const int h   = threadIdx.x;     // 256
    for (int idx = h; idx < 16 * 128; idx += 256)
        sx[idx] = x[(size_t)ni0 * 128 + idx];
    __syncthreads();
    float accP[16], accQ[16];
#pragma unroll
    for (int r = 0; r < 16; r++) { accP[r] = 0.f; accQ[r] = 0.f; }
#pragma unroll 2
    for (int c = 0; c < 128; c++) {
        float wp = W3[c * 256 + h];
        float wq = W3[(128 + c) * 256 + h];
#pragma unroll
        for (int r = 0; r < 16; r++) {
            float xa = sx[r * 128 + c];
            accP[r] += xa * wp;
            accQ[r] += xa * wq;
        }
    }
#pragma unroll
    for (int r = 0; r < 16; r++) {
        P[(size_t)(ni0 + r) * 256 + h] = accP[r];
        Q[(size_t)(ni0 + r) * 256 + h] = accQ[r];
    }
}

// ---------------------------------------------------------------------------
// pair final tiled: 64 CTAs; each handles b, 16 i-rows, all 256 j. P streamed.
__global__ void pair_final2(const float* __restrict__ P,
                            const float* __restrict__ Q,
                            const float* __restrict__ b3,
                            const float* __restrict__ oW,
                            const float* __restrict__ ob,
                            float* __restrict__ out)        // (B,V,V)
{
    __shared__ float sQ[16 * 257];
    __shared__ float sW[256];
    __shared__ float sP[4 * 256];
    const int blk = blockIdx.x;
    const int b   = blk >> 4;
    const int i0  = (blk & 15) * 16;
    const int tid = threadIdx.x;     // 256
    sW[tid] = oW[tid];
    {
        float bb = b3[tid];
#pragma unroll
        for (int r = 0; r < 16; r++)
            sQ[r * 257 + tid] = Q[(size_t)(b * 256 + i0 + r) * 256 + tid] + bb;
    }
    __syncthreads();
    const float outb = ob[0];
    const int ii = tid >> 4;         // 0..15
    const int hg = tid & 15;         // 0..15

    for (int j4 = 0; j4 < 64; j4++) {
        // stage 4 P rows
        const float* psrc = P + (size_t)(b * 256 + j4 * 4) * 256;
#pragma unroll
        for (int t = 0; t < 4; t++)
            sP[t * 256 + tid] = psrc[t * 256 + tid];
        __syncthreads();
#pragma unroll
        for (int jj = 0; jj < 4; jj++) {
            const float* p = sP + jj * 256;
            const float* q = sQ + ii * 257;
            float s = 0.f;
#pragma unroll
            for (int hh = 0; hh < 16; hh++) {
                int h = hh * 16 + hg;
                s += fmaxf(p[h] + q[h], 0.f) * sW[h];
            }
#pragma unroll
            for (int off = 8; off > 0; off >>= 1)
                s += __shfl_down_sync(0xffffffffu, s, off, 16);
            if (hg == 0) {
                float z = s + outb;
                out[(size_t)(b * 256 + i0 + ii) * 256 + j4 * 4 + jj] =
                    1.0f / (1.0f + expf(-z));
            }
        }
        __syncthreads();
    }
}

// ---------------------------------------------------------------------------
extern "C" void kernel_launch(void* const* d_in, const int* in_sizes, int n_in,
                              void* d_out, int out_size)
{
    const int*   adj   = (const int*)  d_in[0];
    const float* x0    = (const float*)d_in[1];
    const float* e     = (const float*)d_in[2];
    const float* ec1W1 = (const float*)d_in[3];
    const float* ec1b1 = (const float*)d_in[4];
    const float* ec1W2 = (const float*)d_in[5];
    const float* ec1b2 = (const float*)d_in[6];
    const float* ec2W1 = (const float*)d_in[7];
    const float* ec2b1 = (const float*)d_in[8];
    const float* ec2W2 = (const float*)d_in[9];
    const float* ec2b2 = (const float*)d_in[10];
    const float* h3W   = (const float*)d_in[11];
    const float* h3b   = (const float*)d_in[12];
    const float* oW    = (const float*)d_in[13];
    const float* ob    = (const float*)d_in[14];
    float* out = (float*)d_out;

    float *gA, *gB, *gx1, *gx2, *gP, *gQ;
    cudaGetSymbolAddress((void**)&gA,  g_A);
    cudaGetSymbolAddress((void**)&gB,  g_Bv);
    cudaGetSymbolAddress((void**)&gx1, g_x1);
    cudaGetSymbolAddress((void**)&gx2, g_x2);
    cudaGetSymbolAddress((void**)&gP,  g_P);
    cudaGetSymbolAddress((void**)&gQ,  g_Q);

    const int nBI = BN * VN;  // 1024
    cudaFuncSetAttribute(fused_ec_mma,
                         cudaFuncAttributeMaxDynamicSharedMemorySize, SMEM_BYTES);

    // EdgeConvE #1
    prep_node2<C1N><<<64, 128>>>(x0, ec1W1, ec1b1, gA, gB);
    fused_ec_mma<<<nBI, 512, SMEM_BYTES>>>(adj, e, gA, gB,
                                           ec1W1 + 2 * C1N * H0N, ec1W2, ec1b2, gx1);
    // EdgeConvE #2
    prep_node2<H0N><<<64, 128>>>(gx1, ec2W1, ec2b1, gA, gB);
    fused_ec_mma<<<nBI, 512, SMEM_BYTES>>>(adj, e, gA, gB,
                                           ec2W1 + 2 * H0N * H0N, ec2W2, ec2b2, gx2);
    // pair scoring
    pair_prep2 <<<64, 256>>>(gx2, h3W, gP, gQ);
    pair_final2<<<64, 256>>>(gP, gQ, h3b, oW, ob, out);
}